// round 2
// baseline (speedup 1.0000x reference)
#include <cuda_runtime.h>

// Fused 2-layer LSTM + time-softmax(last) + dense head + softmax.
// TWO batch elements per warp (shared weight registers, doubled ILP).
// tanh.approx.f32 activations, 2-way split f32x2 FMA chains,
// layer-2 recurrent partial hoisted ahead of layer-1.

#define FULLMASK 0xffffffffu
#define LOG2E 1.4426950408889634f

typedef unsigned long long ull;

static __device__ __forceinline__ ull ffma2(ull a, ull b, ull c) {
    ull d;
    asm("fma.rn.f32x2 %0, %1, %2, %3;" : "=l"(d) : "l"(a), "l"(b), "l"(c));
    return d;
}
static __device__ __forceinline__ ull pack2(float lo, float hi) {
    ull d;
    asm("mov.b64 %0, {%1, %2};" : "=l"(d) : "f"(lo), "f"(hi));
    return d;
}
static __device__ __forceinline__ float2 unpack2(ull v) {
    float lo, hi;
    asm("mov.b64 {%0, %1}, %2;" : "=f"(lo), "=f"(hi) : "l"(v));
    return make_float2(lo, hi);
}
static __device__ __forceinline__ float ex2f(float x) {
    float y; asm("ex2.approx.f32 %0, %1;" : "=f"(y) : "f"(x)); return y;
}
static __device__ __forceinline__ float rcpf(float x) {
    float y; asm("rcp.approx.f32 %0, %1;" : "=f"(y) : "f"(x)); return y;
}
static __device__ __forceinline__ float tanhap(float x) {
    float y; asm("tanh.approx.f32 %0, %1;" : "=f"(y) : "f"(x)); return y;
}

// 8 packed-pair recurrent FMA chain, split across (AL0,AL1)/(AH0,AH1)
#define HH8(WL, WH, AL0, AL1, AH0, AH1, PTR) do {                         \
    const ulonglong2* hp_ = (const ulonglong2*)(PTR);                     \
    ulonglong2 p0 = hp_[0], p1 = hp_[1], p2 = hp_[2], p3 = hp_[3];        \
    AL0 = ffma2(WL[0], p0.x, AL0); AL1 = ffma2(WL[1], p0.y, AL1);         \
    AH0 = ffma2(WH[0], p0.x, AH0); AH1 = ffma2(WH[1], p0.y, AH1);         \
    AL0 = ffma2(WL[2], p1.x, AL0); AL1 = ffma2(WL[3], p1.y, AL1);         \
    AH0 = ffma2(WH[2], p1.x, AH0); AH1 = ffma2(WH[3], p1.y, AH1);         \
    AL0 = ffma2(WL[4], p2.x, AL0); AL1 = ffma2(WL[5], p2.y, AL1);         \
    AH0 = ffma2(WH[4], p2.x, AH0); AH1 = ffma2(WH[5], p2.y, AH1);         \
    AL0 = ffma2(WL[6], p3.x, AL0); AL1 = ffma2(WL[7], p3.y, AL1);         \
    AH0 = ffma2(WH[6], p3.x, AH0); AH1 = ffma2(WH[7], p3.y, AH1);         \
} while (0)

// 5 packed x-pair FMAs (input dim 11 -> 5 pairs + 1 scalar handled outside)
#define IH5(WL, WH, AL0, AL1, AH0, AH1, XQ) do {                          \
    AL0 = ffma2(WL[0], XQ[0], AL0); AL1 = ffma2(WL[1], XQ[1], AL1);       \
    AH0 = ffma2(WH[0], XQ[0], AH0); AH1 = ffma2(WH[1], XQ[1], AH1);       \
    AL0 = ffma2(WL[2], XQ[2], AL0); AL1 = ffma2(WL[3], XQ[3], AL1);       \
    AH0 = ffma2(WH[2], XQ[2], AH0); AH1 = ffma2(WH[3], XQ[3], AH1);       \
    AL0 = ffma2(WL[4], XQ[4], AL0);                                      \
    AH0 = ffma2(WH[4], XQ[4], AH0);                                      \
} while (0)

// gate merge + activations + cell update. EXL/EXH: extra scalar gate terms.
#define GATES(AL0, AL1, AH0, AH1, EXL, EXH, CC, HOUT) do {                \
    float2 u0_ = unpack2(AL0), u1_ = unpack2(AL1);                        \
    float2 v0_ = unpack2(AH0), v1_ = unpack2(AH1);                        \
    float gLo_ = (u0_.x + u1_.x) + (u0_.y + u1_.y) + (EXL);               \
    float gHi_ = (v0_.x + v1_.x) + (v0_.y + v1_.y) + (EXH);               \
    float sA_ = fmaf(0.5f, tanhap(0.5f * gLo_), 0.5f);  /* sigmoid i/f */ \
    float tA_ = fmaf(cA, tanhap(cS * gHi_), cB);        /* tanh g / sig o */ \
    float fg_ = __shfl_down_sync(FULLMASK, sA_, 16);                      \
    float og_ = __shfl_down_sync(FULLMASK, tA_, 16);                      \
    CC = fmaf(fg_, CC, sA_ * tA_);                                        \
    HOUT = og_ * tanhap(CC);                                              \
} while (0)

static __device__ __forceinline__ void dense_head(
    float h2, float ssum, int lane,
    const float* __restrict__ Wd1, const float* __restrict__ bd1,
    const float* __restrict__ Wd2, const float* __restrict__ bd2,
    const float* __restrict__ Wd3, const float* __restrict__ bd3,
    float* __restrict__ out, int b)
{
    float sval = ex2f(h2 * LOG2E) * rcpf(ssum);   // valid on lanes 0..15
    const int j8 = lane & 7;
    float d1 = bd1[j8];
#pragma unroll
    for (int k = 0; k < 16; ++k) {
        float sk = __shfl_sync(FULLMASK, sval, k);
        d1 = fmaf(Wd1[j8 * 16 + k], sk, d1);
    }
    float d2 = bd2[j8];
#pragma unroll
    for (int k = 0; k < 8; ++k) {
        float dk = __shfl_sync(FULLMASK, d1, k);
        d2 = fmaf(Wd2[j8 * 8 + k], dk, d2);
    }
    const int j3 = (lane < 3) ? lane : 0;
    float d3 = bd3[j3];
#pragma unroll
    for (int k = 0; k < 8; ++k) {
        float dk = __shfl_sync(FULLMASK, d2, k);
        d3 = fmaf(Wd3[j3 * 8 + k], dk, d3);
    }
    float v0 = __shfl_sync(FULLMASK, d3, 0);
    float v1 = __shfl_sync(FULLMASK, d3, 1);
    float v2 = __shfl_sync(FULLMASK, d3, 2);
    float m  = fmaxf(v0, fmaxf(v1, v2));
    float e0 = ex2f((v0 - m) * LOG2E);
    float e1 = ex2f((v1 - m) * LOG2E);
    float e2 = ex2f((v2 - m) * LOG2E);
    float inv = rcpf(e0 + e1 + e2);
    if (lane == 0) {
        out[b * 3 + 0] = e0 * inv;
        out[b * 3 + 1] = e1 * inv;
        out[b * 3 + 2] = e2 * inv;
    }
}

__global__ void __launch_bounds__(64, 5)
lstm_fused2_kernel(const float* __restrict__ x,
                   const float* __restrict__ Wih1, const float* __restrict__ Whh1,
                   const float* __restrict__ bih1, const float* __restrict__ bhh1,
                   const float* __restrict__ Wih2, const float* __restrict__ Whh2,
                   const float* __restrict__ bih2, const float* __restrict__ bhh2,
                   const float* __restrict__ Wd1, const float* __restrict__ bd1,
                   const float* __restrict__ Wd2, const float* __restrict__ bd2,
                   const float* __restrict__ Wd3, const float* __restrict__ bd3,
                   float* __restrict__ out)
{
    constexpr int T = 512, IN = 11;
    const int lane = threadIdx.x & 31;
    const int wid  = threadIdx.x >> 5;          // 0..1
    const int bA   = (blockIdx.x * 2 + wid) * 2;
    const int bB   = bA + 1;

    // [warp][elem][phase][unit]
    __shared__ __align__(16) float sh1[2][2][2][16];
    __shared__ __align__(16) float sh2[2][2][2][16];

    const int j = lane, jh = lane + 32;

    // ---- packed weights (shared across both elements) ----
    ull wi1L[5], wi1H[5];
#pragma unroll
    for (int k = 0; k < 5; ++k) {
        wi1L[k] = pack2(Wih1[j  * IN + 2 * k], Wih1[j  * IN + 2 * k + 1]);
        wi1H[k] = pack2(Wih1[jh * IN + 2 * k], Wih1[jh * IN + 2 * k + 1]);
    }
    const float w10L = Wih1[j * IN + 10], w10H = Wih1[jh * IN + 10];

    ull wh1L[8], wh1H[8], wi2L[8], wi2H[8], wh2L[8], wh2H[8];
#pragma unroll
    for (int k = 0; k < 8; ++k) {
        wh1L[k] = pack2(Whh1[j  * 16 + 2 * k], Whh1[j  * 16 + 2 * k + 1]);
        wh1H[k] = pack2(Whh1[jh * 16 + 2 * k], Whh1[jh * 16 + 2 * k + 1]);
        wi2L[k] = pack2(Wih2[j  * 16 + 2 * k], Wih2[j  * 16 + 2 * k + 1]);
        wi2H[k] = pack2(Wih2[jh * 16 + 2 * k], Wih2[jh * 16 + 2 * k + 1]);
        wh2L[k] = pack2(Whh2[j  * 16 + 2 * k], Whh2[j  * 16 + 2 * k + 1]);
        wh2H[k] = pack2(Whh2[jh * 16 + 2 * k], Whh2[jh * 16 + 2 * k + 1]);
    }
    const ull b1L = pack2(bih1[j]  + bhh1[j],  0.f);
    const ull b1H = pack2(bih1[jh] + bhh1[jh], 0.f);
    const ull b2L = pack2(bih2[j]  + bhh2[j],  0.f);
    const ull b2H = pack2(bih2[jh] + bhh2[jh], 0.f);
    const ull Z2  = pack2(0.f, 0.f);

    // hi-gate activation constants: tanh (g) on lanes<16, sigmoid (o) on lanes>=16
    const bool loG = (lane < 16);
    const float cS = loG ? 1.0f : 0.5f;
    const float cA = loG ? 1.0f : 0.5f;
    const float cB = loG ? 0.0f : 0.5f;

    if (lane < 16) {
        sh1[wid][0][0][lane] = 0.f; sh1[wid][1][0][lane] = 0.f;
        sh2[wid][0][0][lane] = 0.f; sh2[wid][1][0][lane] = 0.f;
    }
    __syncwarp();

    const float* xpA = x + (size_t)bA * (T * IN);
    const float* xpB = x + (size_t)bB * (T * IN);
    float cc1A = 0.f, cc2A = 0.f, h2A = 0.f, ssA = 0.f;
    float cc1B = 0.f, cc2B = 0.f, h2B = 0.f, ssB = 0.f;

    for (int t = 0; t < T; ++t) {
        const int rp = t & 1, wp = rp ^ 1;

        // x pairs (warp-uniform broadcast loads), both elements
        ull xqA[5], xqB[5];
#pragma unroll
        for (int k = 0; k < 5; ++k) {
            xqA[k] = pack2(__ldg(xpA + 2 * k), __ldg(xpA + 2 * k + 1));
            xqB[k] = pack2(__ldg(xpB + 2 * k), __ldg(xpB + 2 * k + 1));
        }
        const float x10A = __ldg(xpA + 10), x10B = __ldg(xpB + 10);
        xpA += IN; xpB += IN;

        // ---- layer-2 recurrent partials (independent of this step's layer 1) ----
        ull qAL0 = b2L, qAL1 = Z2, qAH0 = b2H, qAH1 = Z2;
        HH8(wh2L, wh2H, qAL0, qAL1, qAH0, qAH1, &sh2[wid][0][rp][0]);
        ull qBL0 = b2L, qBL1 = Z2, qBH0 = b2H, qBH1 = Z2;
        HH8(wh2L, wh2H, qBL0, qBL1, qBH0, qBH1, &sh2[wid][1][rp][0]);

        // ---- layer 1, elem A ----
        ull aL0 = b1L, aL1 = Z2, aH0 = b1H, aH1 = Z2;
        HH8(wh1L, wh1H, aL0, aL1, aH0, aH1, &sh1[wid][0][rp][0]);
        IH5(wi1L, wi1H, aL0, aL1, aH0, aH1, xqA);
        float h1A;
        GATES(aL0, aL1, aH0, aH1, w10L * x10A, w10H * x10A, cc1A, h1A);
        if (loG) sh1[wid][0][wp][lane] = h1A;

        // ---- layer 1, elem B ----
        ull bL0 = b1L, bL1 = Z2, bH0 = b1H, bH1 = Z2;
        HH8(wh1L, wh1H, bL0, bL1, bH0, bH1, &sh1[wid][1][rp][0]);
        IH5(wi1L, wi1H, bL0, bL1, bH0, bH1, xqB);
        float h1B;
        GATES(bL0, bL1, bH0, bH1, w10L * x10B, w10H * x10B, cc1B, h1B);
        if (loG) sh1[wid][1][wp][lane] = h1B;

        __syncwarp();

        // ---- layer 2 finish, elem A ----
        HH8(wi2L, wi2H, qAL0, qAL1, qAH0, qAH1, &sh1[wid][0][wp][0]);
        GATES(qAL0, qAL1, qAH0, qAH1, 0.f, 0.f, cc2A, h2A);
        if (loG) sh2[wid][0][wp][lane] = h2A;
        ssA += ex2f(h2A * LOG2E);   // h2 in (-1,1): max-free softmax accumulation

        // ---- layer 2 finish, elem B ----
        HH8(wi2L, wi2H, qBL0, qBL1, qBH0, qBH1, &sh1[wid][1][wp][0]);
        GATES(qBL0, qBL1, qBH0, qBH1, 0.f, 0.f, cc2B, h2B);
        if (loG) sh2[wid][1][wp][lane] = h2B;
        ssB += ex2f(h2B * LOG2E);

        __syncwarp();
    }

    dense_head(h2A, ssA, lane, Wd1, bd1, Wd2, bd2, Wd3, bd3, out, bA);
    dense_head(h2B, ssB, lane, Wd1, bd1, Wd2, bd2, Wd3, bd3, out, bB);
}

extern "C" void kernel_launch(void* const* d_in, const int* in_sizes, int n_in,
                              void* d_out, int out_size) {
    (void)in_sizes; (void)n_in; (void)out_size;
    const float* x    = (const float*)d_in[0];
    const float* Wih1 = (const float*)d_in[1];
    const float* Whh1 = (const float*)d_in[2];
    const float* bih1 = (const float*)d_in[3];
    const float* bhh1 = (const float*)d_in[4];
    const float* Wih2 = (const float*)d_in[5];
    const float* Whh2 = (const float*)d_in[6];
    const float* bih2 = (const float*)d_in[7];
    const float* bhh2 = (const float*)d_in[8];
    const float* Wd1  = (const float*)d_in[9];
    const float* bd1  = (const float*)d_in[10];
    const float* Wd2  = (const float*)d_in[11];
    const float* bd2  = (const float*)d_in[12];
    const float* Wd3  = (const float*)d_in[13];
    const float* bd3  = (const float*)d_in[14];
    float* out = (float*)d_out;

    // 4096 batch elems / (2 warps/block * 2 elems/warp) = 1024 blocks
    lstm_fused2_kernel<<<1024, 64>>>(x, Wih1, Whh1, bih1, bhh1,
                                     Wih2, Whh2, bih2, bhh2,
                                     Wd1, bd1, Wd2, bd2, Wd3, bd3, out);
}

// round 3
// speedup vs baseline: 1.1110x; 1.1110x over previous
#include <cuda_runtime.h>

// Two-kernel fused RNN:
//  K1: xg1[b][t] = x[b][t] @ Wih1^T + bih1 + bhh1  (time-parallel, GEMM-like)
//  K2: recurrent 2-layer LSTM with L2(t) || L1(t+1) software pipeline,
//      + time-softmax(last) + dense head + final softmax.
// One warp per batch element in K2; lane j owns gate rows j and j+32.

#define FULLMASK 0xffffffffu
#define LOG2E 1.4426950408889634f

typedef unsigned long long ull;

// 536 MB scratch for precomputed layer-1 input gates (pairs: gate j, gate j+32)
static __device__ float2 g_xg[(size_t)4096 * 512 * 32];

static __device__ __forceinline__ ull ffma2(ull a, ull b, ull c) {
    ull d;
    asm("fma.rn.f32x2 %0, %1, %2, %3;" : "=l"(d) : "l"(a), "l"(b), "l"(c));
    return d;
}
static __device__ __forceinline__ ull pack2(float lo, float hi) {
    ull d;
    asm("mov.b64 %0, {%1, %2};" : "=l"(d) : "f"(lo), "f"(hi));
    return d;
}
static __device__ __forceinline__ float2 unpack2(ull v) {
    float lo, hi;
    asm("mov.b64 {%0, %1}, %2;" : "=f"(lo), "=f"(hi) : "l"(v));
    return make_float2(lo, hi);
}
static __device__ __forceinline__ float ex2f(float x) {
    float y; asm("ex2.approx.f32 %0, %1;" : "=f"(y) : "f"(x)); return y;
}
static __device__ __forceinline__ float rcpf(float x) {
    float y; asm("rcp.approx.f32 %0, %1;" : "=f"(y) : "f"(x)); return y;
}
static __device__ __forceinline__ float tanhap(float x) {
    float y; asm("tanh.approx.f32 %0, %1;" : "=f"(y) : "f"(x)); return y;
}

// ============================ K1: input-gate GEMM ============================
__global__ void __launch_bounds__(256)
xg1_kernel(const float* __restrict__ x,
           const float* __restrict__ Wih1,
           const float* __restrict__ bih1,
           const float* __restrict__ bhh1)
{
    constexpr int IN = 11, TCHUNK = 128;
    const int lane = threadIdx.x & 31;
    const int w    = blockIdx.x * 8 + (threadIdx.x >> 5);  // 0..16383
    const int b    = w >> 2;
    const int t0   = (w & 3) * TCHUNK;

    const int j = lane, jh = lane + 32;
    ull wiL[5], wiH[5];
#pragma unroll
    for (int k = 0; k < 5; ++k) {
        wiL[k] = pack2(Wih1[j  * IN + 2 * k], Wih1[j  * IN + 2 * k + 1]);
        wiH[k] = pack2(Wih1[jh * IN + 2 * k], Wih1[jh * IN + 2 * k + 1]);
    }
    const float w10L = Wih1[j * IN + 10], w10H = Wih1[jh * IN + 10];
    const float bL = bih1[j]  + bhh1[j];
    const float bH = bih1[jh] + bhh1[jh];
    const ull Z2 = pack2(0.f, 0.f);

    const float* xp = x + ((size_t)b * 512 + t0) * IN;
    float2* op = g_xg + ((size_t)b * 512 + t0) * 32 + lane;

    for (int t = 0; t < TCHUNK; ++t) {
        ull xq0 = pack2(__ldg(xp + 0), __ldg(xp + 1));
        ull xq1 = pack2(__ldg(xp + 2), __ldg(xp + 3));
        ull xq2 = pack2(__ldg(xp + 4), __ldg(xp + 5));
        ull xq3 = pack2(__ldg(xp + 6), __ldg(xp + 7));
        ull xq4 = pack2(__ldg(xp + 8), __ldg(xp + 9));
        const float x10 = __ldg(xp + 10);
        xp += IN;

        ull aL0 = Z2, aL1 = Z2, aH0 = Z2, aH1 = Z2;
        aL0 = ffma2(wiL[0], xq0, aL0); aL1 = ffma2(wiL[1], xq1, aL1);
        aH0 = ffma2(wiH[0], xq0, aH0); aH1 = ffma2(wiH[1], xq1, aH1);
        aL0 = ffma2(wiL[2], xq2, aL0); aL1 = ffma2(wiL[3], xq3, aL1);
        aH0 = ffma2(wiH[2], xq2, aH0); aH1 = ffma2(wiH[3], xq3, aH1);
        aL0 = ffma2(wiL[4], xq4, aL0);
        aH0 = ffma2(wiH[4], xq4, aH0);

        float2 u0 = unpack2(aL0), u1 = unpack2(aL1);
        float2 v0 = unpack2(aH0), v1 = unpack2(aH1);
        float gLo = (u0.x + u1.x) + (u0.y + u1.y) + fmaf(w10L, x10, bL);
        float gHi = (v0.x + v1.x) + (v0.y + v1.y) + fmaf(w10H, x10, bH);
        op[0] = make_float2(gLo, gHi);
        op += 32;
    }
}

// ============================ K2: recurrence ============================

// 8 packed-pair FMA chain, 2-way split
#define CHAIN8(WL, WH, AL0, AL1, AH0, AH1, P0, P1, P2, P3) do {           \
    AL0 = ffma2(WL[0], P0.x, AL0); AL1 = ffma2(WL[1], P0.y, AL1);         \
    AH0 = ffma2(WH[0], P0.x, AH0); AH1 = ffma2(WH[1], P0.y, AH1);         \
    AL0 = ffma2(WL[2], P1.x, AL0); AL1 = ffma2(WL[3], P1.y, AL1);         \
    AH0 = ffma2(WH[2], P1.x, AH0); AH1 = ffma2(WH[3], P1.y, AH1);         \
    AL0 = ffma2(WL[4], P2.x, AL0); AL1 = ffma2(WL[5], P2.y, AL1);         \
    AH0 = ffma2(WH[4], P2.x, AH0); AH1 = ffma2(WH[5], P2.y, AH1);         \
    AL0 = ffma2(WL[6], P3.x, AL0); AL1 = ffma2(WL[7], P3.y, AL1);         \
    AH0 = ffma2(WH[6], P3.x, AH0); AH1 = ffma2(WH[7], P3.y, AH1);         \
} while (0)

// 8 packed-pair FMA chain, single accumulator per half (saves registers)
#define CHAIN8S(WL, WH, AL0, AH0, P0, P1, P2, P3) do {                    \
    AL0 = ffma2(WL[0], P0.x, AL0); AH0 = ffma2(WH[0], P0.x, AH0);         \
    AL0 = ffma2(WL[1], P0.y, AL0); AH0 = ffma2(WH[1], P0.y, AH0);         \
    AL0 = ffma2(WL[2], P1.x, AL0); AH0 = ffma2(WH[2], P1.x, AH0);         \
    AL0 = ffma2(WL[3], P1.y, AL0); AH0 = ffma2(WH[3], P1.y, AH0);         \
    AL0 = ffma2(WL[4], P2.x, AL0); AH0 = ffma2(WH[4], P2.x, AH0);         \
    AL0 = ffma2(WL[5], P2.y, AL0); AH0 = ffma2(WH[5], P2.y, AH0);         \
    AL0 = ffma2(WL[6], P3.x, AL0); AH0 = ffma2(WH[6], P3.x, AH0);         \
    AL0 = ffma2(WL[7], P3.y, AL0); AH0 = ffma2(WH[7], P3.y, AH0);         \
} while (0)

// merged gates -> activations -> cell update -> hidden (valid on lanes<16)
#define GATESG(GLO, GHI, CC, HOUT) do {                                   \
    float sA_ = fmaf(0.5f, tanhap(0.5f * (GLO)), 0.5f);                   \
    float tA_ = fmaf(cA, tanhap(cS * (GHI)), cB);                         \
    float fg_ = __shfl_down_sync(FULLMASK, sA_, 16);                      \
    float og_ = __shfl_down_sync(FULLMASK, tA_, 16);                      \
    CC = fmaf(fg_, CC, sA_ * tA_);                                        \
    HOUT = og_ * tanhap(CC);                                              \
} while (0)

__global__ void __launch_bounds__(128, 3)
lstm_rec_kernel(const float* __restrict__ Whh1,
                const float* __restrict__ Wih2, const float* __restrict__ Whh2,
                const float* __restrict__ bih2, const float* __restrict__ bhh2,
                const float* __restrict__ Wd1, const float* __restrict__ bd1,
                const float* __restrict__ Wd2, const float* __restrict__ bd2,
                const float* __restrict__ Wd3, const float* __restrict__ bd3,
                float* __restrict__ out)
{
    constexpr int T = 512;
    const int lane = threadIdx.x & 31;
    const int wid  = threadIdx.x >> 5;
    const int b    = blockIdx.x * 4 + wid;

    __shared__ __align__(16) float h1buf[4][2][16];
    __shared__ __align__(16) float h2buf[4][2][16];

    const int j = lane, jh = lane + 32;

    ull wh1L[8], wh1H[8], wi2L[8], wi2H[8], wh2L[8], wh2H[8];
#pragma unroll
    for (int k = 0; k < 8; ++k) {
        wh1L[k] = pack2(Whh1[j  * 16 + 2 * k], Whh1[j  * 16 + 2 * k + 1]);
        wh1H[k] = pack2(Whh1[jh * 16 + 2 * k], Whh1[jh * 16 + 2 * k + 1]);
        wi2L[k] = pack2(Wih2[j  * 16 + 2 * k], Wih2[j  * 16 + 2 * k + 1]);
        wi2H[k] = pack2(Wih2[jh * 16 + 2 * k], Wih2[jh * 16 + 2 * k + 1]);
        wh2L[k] = pack2(Whh2[j  * 16 + 2 * k], Whh2[j  * 16 + 2 * k + 1]);
        wh2H[k] = pack2(Whh2[jh * 16 + 2 * k], Whh2[jh * 16 + 2 * k + 1]);
    }
    const ull b2L = pack2(bih2[j]  + bhh2[j],  0.f);
    const ull b2H = pack2(bih2[jh] + bhh2[jh], 0.f);
    const ull Z2  = pack2(0.f, 0.f);

    // hi-gate activation constants: tanh (g) on lanes<16, sigmoid (o) on lanes>=16
    const bool loG = (lane < 16);
    const float cS = loG ? 1.0f : 0.5f;
    const float cA = loG ? 1.0f : 0.5f;
    const float cB = loG ? 0.0f : 0.5f;

    const float2* xg = g_xg + (size_t)b * (T * 32) + lane;

    float cc1 = 0.f, cc2 = 0.f, h2 = 0.f, ssum = 0.f;

    // ---- prologue: h1(0) from xg(0) alone (h0 = 0) ----
    {
        float2 x0 = xg[0];
        float h1v;
        GATESG(x0.x, x0.y, cc1, h1v);
        if (loG) h1buf[wid][0][lane] = h1v;
        if (loG) h2buf[wid][1][lane] = 0.f;   // h2(-1)
    }
    __syncwarp();

    // ---- main pipelined loop: L2(t=i) || L1(t=i+1), i = 0..T-2 ----
    for (int i = 0; i < T - 1; ++i) {
        const int pi = i & 1, pn = pi ^ 1;

        // shared h1(i) vectors + h2(i-1) vectors
        const ulonglong2* hp = (const ulonglong2*)(&h1buf[wid][pi][0]);
        ulonglong2 p0 = hp[0], p1 = hp[1], p2 = hp[2], p3 = hp[3];
        const ulonglong2* qp = (const ulonglong2*)(&h2buf[wid][pn][0]);
        ulonglong2 q0 = qp[0], q1 = qp[1], q2 = qp[2], q3 = qp[3];

        float2 xgn = xg[(i + 1) * 32];   // layer-1 input gates for t=i+1

        // L2(i): two recurrent matmuls, 2-way split chains
        ull sL0 = b2L, sL1 = Z2, sH0 = b2H, sH1 = Z2;
        CHAIN8(wi2L, wi2H, sL0, sL1, sH0, sH1, p0, p1, p2, p3);
        CHAIN8(wh2L, wh2H, sL0, sL1, sH0, sH1, q0, q1, q2, q3);

        // L1(i+1): one recurrent matmul, single-acc chains (independent of L2)
        ull tL0 = Z2, tH0 = Z2;
        CHAIN8S(wh1L, wh1H, tL0, tH0, p0, p1, p2, p3);

        // L2 gates -> h2(i)
        {
            float2 u0 = unpack2(sL0), u1 = unpack2(sL1);
            float2 v0 = unpack2(sH0), v1 = unpack2(sH1);
            float gLo = (u0.x + u1.x) + (u0.y + u1.y);
            float gHi = (v0.x + v1.x) + (v0.y + v1.y);
            GATESG(gLo, gHi, cc2, h2);
            if (loG) h2buf[wid][pi][lane] = h2;
            ssum += ex2f(h2 * LOG2E);  // h2 in (-1,1): max-free accumulation
        }
        // L1 gates -> h1(i+1)
        {
            float2 u0 = unpack2(tL0);
            float2 v0 = unpack2(tH0);
            float gLo = u0.x + u0.y + xgn.x;
            float gHi = v0.x + v0.y + xgn.y;
            float h1v;
            GATESG(gLo, gHi, cc1, h1v);
            if (loG) h1buf[wid][pn][lane] = h1v;
        }
        __syncwarp();
    }

    // ---- epilogue: L2(T-1) ----
    {
        const int pi = (T - 1) & 1, pn = pi ^ 1;
        const ulonglong2* hp = (const ulonglong2*)(&h1buf[wid][pi][0]);
        ulonglong2 p0 = hp[0], p1 = hp[1], p2 = hp[2], p3 = hp[3];
        const ulonglong2* qp = (const ulonglong2*)(&h2buf[wid][pn][0]);
        ulonglong2 q0 = qp[0], q1 = qp[1], q2 = qp[2], q3 = qp[3];

        ull sL0 = b2L, sL1 = Z2, sH0 = b2H, sH1 = Z2;
        CHAIN8(wi2L, wi2H, sL0, sL1, sH0, sH1, p0, p1, p2, p3);
        CHAIN8(wh2L, wh2H, sL0, sL1, sH0, sH1, q0, q1, q2, q3);
        float2 u0 = unpack2(sL0), u1 = unpack2(sL1);
        float2 v0 = unpack2(sH0), v1 = unpack2(sH1);
        float gLo = (u0.x + u1.x) + (u0.y + u1.y);
        float gHi = (v0.x + v1.x) + (v0.y + v1.y);
        GATESG(gLo, gHi, cc2, h2);
        ssum += ex2f(h2 * LOG2E);
    }

    // ---- dense head: s = exp(h2_last)/ssum, 3 tiny GEMVs, softmax ----
    float sval = ex2f(h2 * LOG2E) * rcpf(ssum);   // valid on lanes 0..15
    const int j8 = lane & 7;
    float d1 = bd1[j8];
#pragma unroll
    for (int k = 0; k < 16; ++k) {
        float sk = __shfl_sync(FULLMASK, sval, k);
        d1 = fmaf(Wd1[j8 * 16 + k], sk, d1);
    }
    float d2 = bd2[j8];
#pragma unroll
    for (int k = 0; k < 8; ++k) {
        float dk = __shfl_sync(FULLMASK, d1, k);
        d2 = fmaf(Wd2[j8 * 8 + k], dk, d2);
    }
    const int j3 = (lane < 3) ? lane : 0;
    float d3 = bd3[j3];
#pragma unroll
    for (int k = 0; k < 8; ++k) {
        float dk = __shfl_sync(FULLMASK, d2, k);
        d3 = fmaf(Wd3[j3 * 8 + k], dk, d3);
    }
    float v0 = __shfl_sync(FULLMASK, d3, 0);
    float v1 = __shfl_sync(FULLMASK, d3, 1);
    float v2 = __shfl_sync(FULLMASK, d3, 2);
    float m  = fmaxf(v0, fmaxf(v1, v2));
    float e0 = ex2f((v0 - m) * LOG2E);
    float e1 = ex2f((v1 - m) * LOG2E);
    float e2 = ex2f((v2 - m) * LOG2E);
    float inv = rcpf(e0 + e1 + e2);
    if (lane == 0) {
        out[b * 3 + 0] = e0 * inv;
        out[b * 3 + 1] = e1 * inv;
        out[b * 3 + 2] = e2 * inv;
    }
}

extern "C" void kernel_launch(void* const* d_in, const int* in_sizes, int n_in,
                              void* d_out, int out_size) {
    (void)in_sizes; (void)n_in; (void)out_size;
    const float* x    = (const float*)d_in[0];
    const float* Wih1 = (const float*)d_in[1];
    const float* Whh1 = (const float*)d_in[2];
    const float* bih1 = (const float*)d_in[3];
    const float* bhh1 = (const float*)d_in[4];
    const float* Wih2 = (const float*)d_in[5];
    const float* Whh2 = (const float*)d_in[6];
    const float* bih2 = (const float*)d_in[7];
    const float* bhh2 = (const float*)d_in[8];
    const float* Wd1  = (const float*)d_in[9];
    const float* bd1  = (const float*)d_in[10];
    const float* Wd2  = (const float*)d_in[11];
    const float* bd2  = (const float*)d_in[12];
    const float* Wd3  = (const float*)d_in[13];
    const float* bd3  = (const float*)d_in[14];
    float* out = (float*)d_out;

    // K1: 16384 warps (4096 b x 4 chunks of 128 t), 8 warps/block
    xg1_kernel<<<2048, 256>>>(x, Wih1, bih1, bhh1);
    // K2: 4096 warps, 4 per block
    lstm_rec_kernel<<<1024, 128>>>(Whh1, Wih2, Whh2, bih2, bhh2,
                                   Wd1, bd1, Wd2, bd2, Wd3, bd3, out);
}

// round 4
// speedup vs baseline: 2.0096x; 1.8088x over previous
#include <cuda_runtime.h>

// Single fused kernel: 2-layer LSTM (pipelined L2(t-1) || L1(t)) +
// time-softmax(last) + dense head + softmax.
// One warp per batch element. Lane j owns gate rows j (i/f) and j+32 (g/o).
// x is prefetched one 4-step chunk ahead (LDG at chunk top -> STS at chunk end)
// so the recurrent loop never waits on DRAM.

#define FULLMASK 0xffffffffu
#define LOG2E 1.4426950408889634f

typedef unsigned long long ull;

static __device__ __forceinline__ ull ffma2(ull a, ull b, ull c) {
    ull d;
    asm("fma.rn.f32x2 %0, %1, %2, %3;" : "=l"(d) : "l"(a), "l"(b), "l"(c));
    return d;
}
static __device__ __forceinline__ ull pack2(float lo, float hi) {
    ull d;
    asm("mov.b64 %0, {%1, %2};" : "=l"(d) : "f"(lo), "f"(hi));
    return d;
}
static __device__ __forceinline__ float2 unpack2(ull v) {
    float lo, hi;
    asm("mov.b64 {%0, %1}, %2;" : "=f"(lo), "=f"(hi) : "l"(v));
    return make_float2(lo, hi);
}
static __device__ __forceinline__ float ex2f(float x) {
    float y; asm("ex2.approx.f32 %0, %1;" : "=f"(y) : "f"(x)); return y;
}
static __device__ __forceinline__ float rcpf(float x) {
    float y; asm("rcp.approx.f32 %0, %1;" : "=f"(y) : "f"(x)); return y;
}
static __device__ __forceinline__ float tanhap(float x) {
    float y; asm("tanh.approx.f32 %0, %1;" : "=f"(y) : "f"(x)); return y;
}

// 8 packed-pair FMA chain, 2-way split accumulators
#define CHAIN8(WL, WH, AL0, AL1, AH0, AH1, P0, P1, P2, P3) do {           \
    AL0 = ffma2(WL[0], P0.x, AL0); AL1 = ffma2(WL[1], P0.y, AL1);         \
    AH0 = ffma2(WH[0], P0.x, AH0); AH1 = ffma2(WH[1], P0.y, AH1);         \
    AL0 = ffma2(WL[2], P1.x, AL0); AL1 = ffma2(WL[3], P1.y, AL1);         \
    AH0 = ffma2(WH[2], P1.x, AH0); AH1 = ffma2(WH[3], P1.y, AH1);         \
    AL0 = ffma2(WL[4], P2.x, AL0); AL1 = ffma2(WL[5], P2.y, AL1);         \
    AH0 = ffma2(WH[4], P2.x, AH0); AH1 = ffma2(WH[5], P2.y, AH1);         \
    AL0 = ffma2(WL[6], P3.x, AL0); AL1 = ffma2(WL[7], P3.y, AL1);         \
    AH0 = ffma2(WH[6], P3.x, AH0); AH1 = ffma2(WH[7], P3.y, AH1);         \
} while (0)

// 8 packed-pair FMA chain, single accumulator per half
#define CHAIN8S(WL, WH, AL0, AH0, P0, P1, P2, P3) do {                    \
    AL0 = ffma2(WL[0], P0.x, AL0); AH0 = ffma2(WH[0], P0.x, AH0);         \
    AL0 = ffma2(WL[1], P0.y, AL0); AH0 = ffma2(WH[1], P0.y, AH0);         \
    AL0 = ffma2(WL[2], P1.x, AL0); AH0 = ffma2(WH[2], P1.x, AH0);         \
    AL0 = ffma2(WL[3], P1.y, AL0); AH0 = ffma2(WH[3], P1.y, AH0);         \
    AL0 = ffma2(WL[4], P2.x, AL0); AH0 = ffma2(WH[4], P2.x, AH0);         \
    AL0 = ffma2(WL[5], P2.y, AL0); AH0 = ffma2(WH[5], P2.y, AH0);         \
    AL0 = ffma2(WL[6], P3.x, AL0); AH0 = ffma2(WH[6], P3.x, AH0);         \
    AL0 = ffma2(WL[7], P3.y, AL0); AH0 = ffma2(WH[7], P3.y, AH0);         \
} while (0)

// merged gates -> activations -> cell update -> hidden (valid on lanes<16)
#define GATESG(GLO, GHI, CC, HOUT) do {                                   \
    float sA_ = fmaf(0.5f, tanhap(0.5f * (GLO)), 0.5f);                   \
    float tA_ = fmaf(cA, tanhap(cS * (GHI)), cB);                         \
    float fg_ = __shfl_down_sync(FULLMASK, sA_, 16);                      \
    float og_ = __shfl_down_sync(FULLMASK, tA_, 16);                      \
    CC = fmaf(fg_, CC, sA_ * tA_);                                        \
    HOUT = og_ * tanhap(CC);                                              \
} while (0)

__global__ void __launch_bounds__(128, 3)
lstm_all_kernel(const float* __restrict__ x,
                const float* __restrict__ Wih1, const float* __restrict__ Whh1,
                const float* __restrict__ bih1, const float* __restrict__ bhh1,
                const float* __restrict__ Wih2, const float* __restrict__ Whh2,
                const float* __restrict__ bih2, const float* __restrict__ bhh2,
                const float* __restrict__ Wd1, const float* __restrict__ bd1,
                const float* __restrict__ Wd2, const float* __restrict__ bd2,
                const float* __restrict__ Wd3, const float* __restrict__ bd3,
                float* __restrict__ out)
{
    constexpr int T = 512, IN = 11;
    const int lane = threadIdx.x & 31;
    const int wid  = threadIdx.x >> 5;
    const int b    = blockIdx.x * 4 + wid;

    // per-warp staging: [phase][4 steps][12 padded floats]
    __shared__ __align__(16) float xstage[4][2][48];
    __shared__ __align__(16) float h1buf[4][2][16];
    __shared__ __align__(16) float h2buf[4][2][16];

    const int j = lane, jh = lane + 32;

    // ---- packed weights ----
    ull wi1L[5], wi1H[5];
#pragma unroll
    for (int k = 0; k < 5; ++k) {
        wi1L[k] = pack2(Wih1[j  * IN + 2 * k], Wih1[j  * IN + 2 * k + 1]);
        wi1H[k] = pack2(Wih1[jh * IN + 2 * k], Wih1[jh * IN + 2 * k + 1]);
    }
    const float w10L = Wih1[j * IN + 10], w10H = Wih1[jh * IN + 10];

    ull wh1L[8], wh1H[8], wi2L[8], wi2H[8], wh2L[8], wh2H[8];
#pragma unroll
    for (int k = 0; k < 8; ++k) {
        wh1L[k] = pack2(Whh1[j  * 16 + 2 * k], Whh1[j  * 16 + 2 * k + 1]);
        wh1H[k] = pack2(Whh1[jh * 16 + 2 * k], Whh1[jh * 16 + 2 * k + 1]);
        wi2L[k] = pack2(Wih2[j  * 16 + 2 * k], Wih2[j  * 16 + 2 * k + 1]);
        wi2H[k] = pack2(Wih2[jh * 16 + 2 * k], Wih2[jh * 16 + 2 * k + 1]);
        wh2L[k] = pack2(Whh2[j  * 16 + 2 * k], Whh2[j  * 16 + 2 * k + 1]);
        wh2H[k] = pack2(Whh2[jh * 16 + 2 * k], Whh2[jh * 16 + 2 * k + 1]);
    }
    const ull b1L = pack2(bih1[j]  + bhh1[j],  0.f);
    const ull b1H = pack2(bih1[jh] + bhh1[jh], 0.f);
    const ull b2L = pack2(bih2[j]  + bhh2[j],  0.f);
    const ull b2H = pack2(bih2[jh] + bhh2[jh], 0.f);
    const ull Z2  = pack2(0.f, 0.f);

    // hi-gate activation constants: tanh (g) on lanes<16, sigmoid (o) on lanes>=16
    const bool loG = (lane < 16);
    const float cS = loG ? 1.0f : 0.5f;
    const float cA = loG ? 1.0f : 0.5f;
    const float cB = loG ? 0.0f : 0.5f;

    const float* xb = x + (size_t)b * (T * IN);

    // ---- stage chunk 0 (t = 0..3) ----
    if (lane < IN) {
#pragma unroll
        for (int s = 0; s < 4; ++s)
            xstage[wid][0][s * 12 + lane] = __ldg(xb + s * IN + lane);
    }
    if (loG) h2buf[wid][1][lane] = 0.f;   // h2(-1) at phase 1
    __syncwarp();

    float cc1 = 0.f, cc2 = 0.f, h2 = 0.f, ssum = 0.f;

    // ---- prologue: h1(0) from x(0) alone (h0 = 0) ----
    {
        const float* xs = &xstage[wid][0][0];
        ull a0 = b1L, aH0 = b1H;
#pragma unroll
        for (int k = 0; k < 5; ++k) {
            ull xq = *(const ull*)(xs + 2 * k);
            a0  = ffma2(wi1L[k], xq, a0);
            aH0 = ffma2(wi1H[k], xq, aH0);
        }
        const float x10 = xs[10];
        float2 u = unpack2(a0), v = unpack2(aH0);
        float gLo = u.x + u.y + w10L * x10;
        float gHi = v.x + v.y + w10H * x10;
        float h1v;
        GATESG(gLo, gHi, cc1, h1v);
        if (loG) h1buf[wid][0][lane] = h1v;
    }
    __syncwarp();

    // ---- main loop: chunks of 4 steps; t = 4c+s; iter does L2(t-1) || L1(t) ----
    for (int c = 0; c < 128; ++c) {
        // prefetch next chunk's x into registers (consumed >=4 steps later)
        float px0, px1, px2, px3;
        if (c < 127 && lane < IN) {
            const float* xp = xb + (4 * (c + 1)) * IN + lane;
            px0 = __ldg(xp);
            px1 = __ldg(xp + IN);
            px2 = __ldg(xp + 2 * IN);
            px3 = __ldg(xp + 3 * IN);
        }
        const float* xs = &xstage[wid][c & 1][0];

#pragma unroll
        for (int s = 0; s < 4; ++s) {
            const int t = 4 * c + s;
            if (c == 0 && s == 0) continue;   // t=0 handled in prologue
            const int i = t - 1;
            const int pi = i & 1, pn = pi ^ 1;

            const ulonglong2* hp = (const ulonglong2*)(&h1buf[wid][pi][0]);
            ulonglong2 p0 = hp[0], p1 = hp[1], p2 = hp[2], p3 = hp[3];
            const ulonglong2* qp = (const ulonglong2*)(&h2buf[wid][pn][0]);
            ulonglong2 q0 = qp[0], q1 = qp[1], q2 = qp[2], q3 = qp[3];

            // L2(i): two recurrent matmuls, 2-way split chains
            ull sL0 = b2L, sL1 = Z2, sH0 = b2H, sH1 = Z2;
            CHAIN8(wi2L, wi2H, sL0, sL1, sH0, sH1, p0, p1, p2, p3);
            CHAIN8(wh2L, wh2H, sL0, sL1, sH0, sH1, q0, q1, q2, q3);

            // L1(t): recurrent matmul + input gates (independent of L2)
            ull tL0 = b1L, tH0 = b1H;
            CHAIN8S(wh1L, wh1H, tL0, tH0, p0, p1, p2, p3);
            const float* xr = xs + s * 12;
#pragma unroll
            for (int k = 0; k < 5; ++k) {
                ull xq = *(const ull*)(xr + 2 * k);
                tL0 = ffma2(wi1L[k], xq, tL0);
                tH0 = ffma2(wi1H[k], xq, tH0);
            }
            const float x10 = xr[10];

            // L2 gates -> h2(i)
            {
                float2 u0 = unpack2(sL0), u1 = unpack2(sL1);
                float2 v0 = unpack2(sH0), v1 = unpack2(sH1);
                float gLo = (u0.x + u1.x) + (u0.y + u1.y);
                float gHi = (v0.x + v1.x) + (v0.y + v1.y);
                GATESG(gLo, gHi, cc2, h2);
                if (loG) h2buf[wid][pi][lane] = h2;
                ssum += ex2f(h2 * LOG2E);  // h2 in (-1,1): max-free accumulation
            }
            // L1 gates -> h1(t)
            {
                float2 u0 = unpack2(tL0);
                float2 v0 = unpack2(tH0);
                float gLo = u0.x + u0.y + w10L * x10;
                float gHi = v0.x + v0.y + w10H * x10;
                float h1v;
                GATESG(gLo, gHi, cc1, h1v);
                if (loG) h1buf[wid][pn][lane] = h1v;
            }
            __syncwarp();
        }

        // commit prefetched x to the other stage buffer
        if (c < 127 && lane < IN) {
            float* xw = &xstage[wid][(c + 1) & 1][lane];
            xw[0]  = px0;
            xw[12] = px1;
            xw[24] = px2;
            xw[36] = px3;
        }
        __syncwarp();
    }

    // ---- epilogue: L2(T-1) ----
    {
        const int pi = (T - 1) & 1, pn = pi ^ 1;
        const ulonglong2* hp = (const ulonglong2*)(&h1buf[wid][pi][0]);
        ulonglong2 p0 = hp[0], p1 = hp[1], p2 = hp[2], p3 = hp[3];
        const ulonglong2* qp = (const ulonglong2*)(&h2buf[wid][pn][0]);
        ulonglong2 q0 = qp[0], q1 = qp[1], q2 = qp[2], q3 = qp[3];

        ull sL0 = b2L, sL1 = Z2, sH0 = b2H, sH1 = Z2;
        CHAIN8(wi2L, wi2H, sL0, sL1, sH0, sH1, p0, p1, p2, p3);
        CHAIN8(wh2L, wh2H, sL0, sL1, sH0, sH1, q0, q1, q2, q3);
        float2 u0 = unpack2(sL0), u1 = unpack2(sL1);
        float2 v0 = unpack2(sH0), v1 = unpack2(sH1);
        float gLo = (u0.x + u1.x) + (u0.y + u1.y);
        float gHi = (v0.x + v1.x) + (v0.y + v1.y);
        GATESG(gLo, gHi, cc2, h2);
        ssum += ex2f(h2 * LOG2E);
    }

    // ---- dense head: s = exp(h2_last)/ssum, 3 tiny GEMVs, softmax ----
    float sval = ex2f(h2 * LOG2E) * rcpf(ssum);   // valid on lanes 0..15
    const int j8 = lane & 7;
    float d1 = bd1[j8];
#pragma unroll
    for (int k = 0; k < 16; ++k) {
        float sk = __shfl_sync(FULLMASK, sval, k);
        d1 = fmaf(Wd1[j8 * 16 + k], sk, d1);
    }
    float d2 = bd2[j8];
#pragma unroll
    for (int k = 0; k < 8; ++k) {
        float dk = __shfl_sync(FULLMASK, d1, k);
        d2 = fmaf(Wd2[j8 * 8 + k], dk, d2);
    }
    const int j3 = (lane < 3) ? lane : 0;
    float d3 = bd3[j3];
#pragma unroll
    for (int k = 0; k < 8; ++k) {
        float dk = __shfl_sync(FULLMASK, d2, k);
        d3 = fmaf(Wd3[j3 * 8 + k], dk, d3);
    }
    float v0 = __shfl_sync(FULLMASK, d3, 0);
    float v1 = __shfl_sync(FULLMASK, d3, 1);
    float v2 = __shfl_sync(FULLMASK, d3, 2);
    float m  = fmaxf(v0, fmaxf(v1, v2));
    float e0 = ex2f((v0 - m) * LOG2E);
    float e1 = ex2f((v1 - m) * LOG2E);
    float e2 = ex2f((v2 - m) * LOG2E);
    float inv = rcpf(e0 + e1 + e2);
    if (lane == 0) {
        out[b * 3 + 0] = e0 * inv;
        out[b * 3 + 1] = e1 * inv;
        out[b * 3 + 2] = e2 * inv;
    }
}

extern "C" void kernel_launch(void* const* d_in, const int* in_sizes, int n_in,
                              void* d_out, int out_size) {
    (void)in_sizes; (void)n_in; (void)out_size;
    const float* x    = (const float*)d_in[0];
    const float* Wih1 = (const float*)d_in[1];
    const float* Whh1 = (const float*)d_in[2];
    const float* bih1 = (const float*)d_in[3];
    const float* bhh1 = (const float*)d_in[4];
    const float* Wih2 = (const float*)d_in[5];
    const float* Whh2 = (const float*)d_in[6];
    const float* bih2 = (const float*)d_in[7];
    const float* bhh2 = (const float*)d_in[8];
    const float* Wd1  = (const float*)d_in[9];
    const float* bd1  = (const float*)d_in[10];
    const float* Wd2  = (const float*)d_in[11];
    const float* bd2  = (const float*)d_in[12];
    const float* Wd3  = (const float*)d_in[13];
    const float* bd3  = (const float*)d_in[14];
    float* out = (float*)d_out;

    lstm_all_kernel<<<1024, 128>>>(x, Wih1, Whh1, bih1, bhh1,
                                   Wih2, Whh2, bih2, bhh2,
                                   Wd1, bd1, Wd2, bd2, Wd3, bd3, out);
}

// round 5
// speedup vs baseline: 2.6122x; 1.2999x over previous
#include <cuda_runtime.h>
#include <cuda_bf16.h>

// Fused 2-layer LSTM (pipelined L2(t-1) || L1(t)) + time-softmax(last) +
// dense head + softmax. One warp per batch element.
// Weights / h-exchange / x-staging in bf16x2 (fma.rn.bf16x2 chains) to halve
// register pressure -> 4 CTAs/SM. Cell state + activations stay fp32.

#define FULLMASK 0xffffffffu
#define LOG2E 1.4426950408889634f

typedef unsigned int u32;

static __device__ __forceinline__ u32 hfma2b(u32 a, u32 b, u32 c) {
    u32 d;
    asm("fma.rn.bf16x2 %0, %1, %2, %3;" : "=r"(d) : "r"(a), "r"(b), "r"(c));
    return d;
}
static __device__ __forceinline__ u32 haddb2(u32 a, u32 b) {
    u32 d;
    asm("add.rn.bf16x2 %0, %1, %2;" : "=r"(d) : "r"(a), "r"(b));
    return d;
}
// pack two f32 -> bf16x2 {lo, hi}
static __device__ __forceinline__ u32 packb2(float lo, float hi) {
    u32 d;
    asm("cvt.rn.bf16x2.f32 %0, %1, %2;" : "=r"(d) : "f"(hi), "f"(lo));
    return d;
}
static __device__ __forceinline__ float2 unpackb2(u32 v) {
    __nv_bfloat162 h = *reinterpret_cast<__nv_bfloat162*>(&v);
    return make_float2(__low2float(h), __high2float(h));
}
static __device__ __forceinline__ float ex2f(float x) {
    float y; asm("ex2.approx.f32 %0, %1;" : "=f"(y) : "f"(x)); return y;
}
static __device__ __forceinline__ float rcpf(float x) {
    float y; asm("rcp.approx.f32 %0, %1;" : "=f"(y) : "f"(x)); return y;
}
static __device__ __forceinline__ float tanhap(float x) {
    float y; asm("tanh.approx.f32 %0, %1;" : "=f"(y) : "f"(x)); return y;
}

// 8-pair bf16x2 FMA chain, 2-way split accumulators
#define BCH8(W, A0, A1, PP) do {                                          \
    A0 = hfma2b(W[0], PP[0], A0); A1 = hfma2b(W[1], PP[1], A1);           \
    A0 = hfma2b(W[2], PP[2], A0); A1 = hfma2b(W[3], PP[3], A1);           \
    A0 = hfma2b(W[4], PP[4], A0); A1 = hfma2b(W[5], PP[5], A1);           \
    A0 = hfma2b(W[6], PP[6], A0); A1 = hfma2b(W[7], PP[7], A1);           \
} while (0)

// merge split bf16x2 accumulators -> f32 gate value
#define BMERGE(A0, A1, G) do {                                            \
    float2 f_ = unpackb2(haddb2(A0, A1));                                 \
    G = f_.x + f_.y;                                                      \
} while (0)

// merged gates -> activations -> cell update -> hidden (valid on lanes<16)
#define GATESG(GLO, GHI, CC, HOUT) do {                                   \
    float sA_ = fmaf(0.5f, tanhap(0.5f * (GLO)), 0.5f);                   \
    float tA_ = fmaf(cA, tanhap(cS * (GHI)), cB);                         \
    float fg_ = __shfl_down_sync(FULLMASK, sA_, 16);                      \
    float og_ = __shfl_down_sync(FULLMASK, tA_, 16);                      \
    CC = fmaf(fg_, CC, sA_ * tA_);                                        \
    HOUT = og_ * tanhap(CC);                                              \
} while (0)

// pack h (lanes<16, fp32) into 8 bf16x2 pairs at BUF (u32*)
#define STORE_HPAIRS(HV, BUF) do {                                        \
    float hb_ = __shfl_down_sync(FULLMASK, HV, 1);                        \
    if (loG && !(lane & 1)) (BUF)[lane >> 1] = packb2(HV, hb_);           \
} while (0)

__global__ void __launch_bounds__(128, 4)
lstm_bf16_kernel(const float* __restrict__ x,
                 const float* __restrict__ Wih1, const float* __restrict__ Whh1,
                 const float* __restrict__ bih1, const float* __restrict__ bhh1,
                 const float* __restrict__ Wih2, const float* __restrict__ Whh2,
                 const float* __restrict__ bih2, const float* __restrict__ bhh2,
                 const float* __restrict__ Wd1, const float* __restrict__ bd1,
                 const float* __restrict__ Wd2, const float* __restrict__ bd2,
                 const float* __restrict__ Wd3, const float* __restrict__ bd3,
                 float* __restrict__ out)
{
    constexpr int T = 512, IN = 11;
    const int lane = threadIdx.x & 31;
    const int wid  = threadIdx.x >> 5;
    const int b    = blockIdx.x * 4 + wid;

    // staging (per warp): x pairs [phase][4 steps][8 u32], h pairs [phase][8 u32]
    __shared__ __align__(16) u32 xstage[4][2][32];
    __shared__ __align__(16) u32 h1buf[4][2][8];
    __shared__ __align__(16) u32 h2buf[4][2][8];

    const int j = lane, jh = lane + 32;

    // ---- packed bf16x2 weights ----
    u32 wi1L[6], wi1H[6];
#pragma unroll
    for (int k = 0; k < 5; ++k) {
        wi1L[k] = packb2(Wih1[j  * IN + 2 * k], Wih1[j  * IN + 2 * k + 1]);
        wi1H[k] = packb2(Wih1[jh * IN + 2 * k], Wih1[jh * IN + 2 * k + 1]);
    }
    wi1L[5] = packb2(Wih1[j  * IN + 10], 0.f);
    wi1H[5] = packb2(Wih1[jh * IN + 10], 0.f);

    u32 wh1L[8], wh1H[8], wi2L[8], wi2H[8], wh2L[8], wh2H[8];
#pragma unroll
    for (int k = 0; k < 8; ++k) {
        wh1L[k] = packb2(Whh1[j  * 16 + 2 * k], Whh1[j  * 16 + 2 * k + 1]);
        wh1H[k] = packb2(Whh1[jh * 16 + 2 * k], Whh1[jh * 16 + 2 * k + 1]);
        wi2L[k] = packb2(Wih2[j  * 16 + 2 * k], Wih2[j  * 16 + 2 * k + 1]);
        wi2H[k] = packb2(Wih2[jh * 16 + 2 * k], Wih2[jh * 16 + 2 * k + 1]);
        wh2L[k] = packb2(Whh2[j  * 16 + 2 * k], Whh2[j  * 16 + 2 * k + 1]);
        wh2H[k] = packb2(Whh2[jh * 16 + 2 * k], Whh2[jh * 16 + 2 * k + 1]);
    }
    // biases kept in f32, added at gate merge
    const float b1Lf = bih1[j]  + bhh1[j];
    const float b1Hf = bih1[jh] + bhh1[jh];
    const float b2Lf = bih2[j]  + bhh2[j];
    const float b2Hf = bih2[jh] + bhh2[jh];

    // hi-gate activation constants: tanh (g) on lanes<16, sigmoid (o) on lanes>=16
    const bool loG = (lane < 16);
    const float cS = loG ? 1.0f : 0.5f;
    const float cA = loG ? 1.0f : 0.5f;
    const float cB = loG ? 0.0f : 0.5f;

    const float* xb = x + (size_t)b * (T * IN);

    // ---- stage chunk 0 (t = 0..3) as bf16x2 pairs ----
    {
        float v[4];
#pragma unroll
        for (int s = 0; s < 4; ++s)
            v[s] = (lane < IN) ? __ldg(xb + s * IN + lane) : 0.f;
#pragma unroll
        for (int s = 0; s < 4; ++s) {
            float hb = __shfl_down_sync(FULLMASK, v[s], 1);
            if (lane < IN && !(lane & 1))
                xstage[wid][0][s * 8 + (lane >> 1)] = packb2(v[s], hb);
        }
    }
    if (loG && !(lane & 1)) h2buf[wid][1][lane >> 1] = 0;   // h2(-1), phase 1
    __syncwarp();

    float cc1 = 0.f, cc2 = 0.f, h2 = 0.f, ssum = 0.f;

    // ---- prologue: h1(0) from x(0) alone (h0 = 0) ----
    {
        const u32* xr = &xstage[wid][0][0];
        uint4 xa = *(const uint4*)xr;
        uint2 xc = *(const uint2*)(xr + 4);
        u32 xq[6] = {xa.x, xa.y, xa.z, xa.w, xc.x, xc.y};
        u32 tL0 = 0, tL1 = 0, tH0 = 0, tH1 = 0;
        tL0 = hfma2b(wi1L[0], xq[0], tL0); tL1 = hfma2b(wi1L[1], xq[1], tL1);
        tH0 = hfma2b(wi1H[0], xq[0], tH0); tH1 = hfma2b(wi1H[1], xq[1], tH1);
        tL0 = hfma2b(wi1L[2], xq[2], tL0); tL1 = hfma2b(wi1L[3], xq[3], tL1);
        tH0 = hfma2b(wi1H[2], xq[2], tH0); tH1 = hfma2b(wi1H[3], xq[3], tH1);
        tL0 = hfma2b(wi1L[4], xq[4], tL0); tL1 = hfma2b(wi1L[5], xq[5], tL1);
        tH0 = hfma2b(wi1H[4], xq[4], tH0); tH1 = hfma2b(wi1H[5], xq[5], tH1);
        float gLo, gHi;
        BMERGE(tL0, tL1, gLo); gLo += b1Lf;
        BMERGE(tH0, tH1, gHi); gHi += b1Hf;
        float h1v;
        GATESG(gLo, gHi, cc1, h1v);
        STORE_HPAIRS(h1v, &h1buf[wid][0][0]);
    }
    __syncwarp();

    // ---- main loop: chunks of 4 steps; iter does L2(t-1) || L1(t) ----
    for (int c = 0; c < 128; ++c) {
        // prefetch next chunk's x into registers (consumed >= 4 steps later)
        float px0, px1, px2, px3;
        px0 = px1 = px2 = px3 = 0.f;
        if (c < 127 && lane < IN) {
            const float* xp = xb + (4 * (c + 1)) * IN + lane;
            px0 = __ldg(xp);
            px1 = __ldg(xp + IN);
            px2 = __ldg(xp + 2 * IN);
            px3 = __ldg(xp + 3 * IN);
        }
        const u32* xs = &xstage[wid][c & 1][0];

#pragma unroll
        for (int s = 0; s < 4; ++s) {
            const int t = 4 * c + s;
            if (c == 0 && s == 0) continue;   // t=0 handled in prologue
            const int i = t - 1;
            const int pi = i & 1, pn = pi ^ 1;

            // broadcast h1(i), h2(i-1) pairs
            const uint4* hp = (const uint4*)(&h1buf[wid][pi][0]);
            uint4 ha = hp[0], hb = hp[1];
            u32 pp[8] = {ha.x, ha.y, ha.z, ha.w, hb.x, hb.y, hb.z, hb.w};
            const uint4* qp = (const uint4*)(&h2buf[wid][pn][0]);
            uint4 qa = qp[0], qb = qp[1];
            u32 qq[8] = {qa.x, qa.y, qa.z, qa.w, qb.x, qb.y, qb.z, qb.w};

            // L2(i): wi2·h1(i) + wh2·h2(i-1)
            u32 sL0 = 0, sL1 = 0, sH0 = 0, sH1 = 0;
            BCH8(wi2L, sL0, sL1, pp);
            BCH8(wi2H, sH0, sH1, pp);
            BCH8(wh2L, sL0, sL1, qq);
            BCH8(wh2H, sH0, sH1, qq);

            // L1(t): wh1·h1(i) + wi1·x(t)  (independent of L2)
            u32 tL0 = 0, tL1 = 0, tH0 = 0, tH1 = 0;
            BCH8(wh1L, tL0, tL1, pp);
            BCH8(wh1H, tH0, tH1, pp);
            {
                const u32* xr = xs + s * 8;
                uint4 xa = *(const uint4*)xr;
                uint2 xc = *(const uint2*)(xr + 4);
                tL0 = hfma2b(wi1L[0], xa.x, tL0); tL1 = hfma2b(wi1L[1], xa.y, tL1);
                tH0 = hfma2b(wi1H[0], xa.x, tH0); tH1 = hfma2b(wi1H[1], xa.y, tH1);
                tL0 = hfma2b(wi1L[2], xa.z, tL0); tL1 = hfma2b(wi1L[3], xa.w, tL1);
                tH0 = hfma2b(wi1H[2], xa.z, tH0); tH1 = hfma2b(wi1H[3], xa.w, tH1);
                tL0 = hfma2b(wi1L[4], xc.x, tL0); tL1 = hfma2b(wi1L[5], xc.y, tL1);
                tH0 = hfma2b(wi1H[4], xc.x, tH0); tH1 = hfma2b(wi1H[5], xc.y, tH1);
            }

            // L2 gates -> h2(i)
            {
                float gLo, gHi;
                BMERGE(sL0, sL1, gLo); gLo += b2Lf;
                BMERGE(sH0, sH1, gHi); gHi += b2Hf;
                GATESG(gLo, gHi, cc2, h2);
                STORE_HPAIRS(h2, &h2buf[wid][pi][0]);
                ssum += ex2f(h2 * LOG2E);  // h2 in (-1,1): max-free accumulation
            }
            // L1 gates -> h1(t)
            {
                float gLo, gHi;
                BMERGE(tL0, tL1, gLo); gLo += b1Lf;
                BMERGE(tH0, tH1, gHi); gHi += b1Hf;
                float h1v;
                GATESG(gLo, gHi, cc1, h1v);
                STORE_HPAIRS(h1v, &h1buf[wid][pn][0]);
            }
            __syncwarp();
        }

        // commit prefetched x (packed bf16x2) to the other stage buffer
        {
            const int ph = (c + 1) & 1;
            float hbv;
            hbv = __shfl_down_sync(FULLMASK, px0, 1);
            if (c < 127 && lane < IN && !(lane & 1))
                xstage[wid][ph][0 * 8 + (lane >> 1)] = packb2(px0, hbv);
            hbv = __shfl_down_sync(FULLMASK, px1, 1);
            if (c < 127 && lane < IN && !(lane & 1))
                xstage[wid][ph][1 * 8 + (lane >> 1)] = packb2(px1, hbv);
            hbv = __shfl_down_sync(FULLMASK, px2, 1);
            if (c < 127 && lane < IN && !(lane & 1))
                xstage[wid][ph][2 * 8 + (lane >> 1)] = packb2(px2, hbv);
            hbv = __shfl_down_sync(FULLMASK, px3, 1);
            if (c < 127 && lane < IN && !(lane & 1))
                xstage[wid][ph][3 * 8 + (lane >> 1)] = packb2(px3, hbv);
        }
        __syncwarp();
    }

    // ---- epilogue: L2(T-1) ----
    {
        const int pi = (T - 1) & 1, pn = pi ^ 1;
        const uint4* hp = (const uint4*)(&h1buf[wid][pi][0]);
        uint4 ha = hp[0], hb = hp[1];
        u32 pp[8] = {ha.x, ha.y, ha.z, ha.w, hb.x, hb.y, hb.z, hb.w};
        const uint4* qp = (const uint4*)(&h2buf[wid][pn][0]);
        uint4 qa = qp[0], qb = qp[1];
        u32 qq[8] = {qa.x, qa.y, qa.z, qa.w, qb.x, qb.y, qb.z, qb.w};

        u32 sL0 = 0, sL1 = 0, sH0 = 0, sH1 = 0;
        BCH8(wi2L, sL0, sL1, pp);
        BCH8(wi2H, sH0, sH1, pp);
        BCH8(wh2L, sL0, sL1, qq);
        BCH8(wh2H, sH0, sH1, qq);
        float gLo, gHi;
        BMERGE(sL0, sL1, gLo); gLo += b2Lf;
        BMERGE(sH0, sH1, gHi); gHi += b2Hf;
        GATESG(gLo, gHi, cc2, h2);
        ssum += ex2f(h2 * LOG2E);
    }

    // ---- dense head (fp32): s = exp(h2_last)/ssum, 3 tiny GEMVs, softmax ----
    float sval = ex2f(h2 * LOG2E) * rcpf(ssum);   // valid on lanes 0..15
    const int j8 = lane & 7;
    float d1 = bd1[j8];
#pragma unroll
    for (int k = 0; k < 16; ++k) {
        float sk = __shfl_sync(FULLMASK, sval, k);
        d1 = fmaf(Wd1[j8 * 16 + k], sk, d1);
    }
    float d2 = bd2[j8];
#pragma unroll
    for (int k = 0; k < 8; ++k) {
        float dk = __shfl_sync(FULLMASK, d1, k);
        d2 = fmaf(Wd2[j8 * 8 + k], dk, d2);
    }
    const int j3 = (lane < 3) ? lane : 0;
    float d3 = bd3[j3];
#pragma unroll
    for (int k = 0; k < 8; ++k) {
        float dk = __shfl_sync(FULLMASK, d2, k);
        d3 = fmaf(Wd3[j3 * 8 + k], dk, d3);
    }
    float v0 = __shfl_sync(FULLMASK, d3, 0);
    float v1 = __shfl_sync(FULLMASK, d3, 1);
    float v2 = __shfl_sync(FULLMASK, d3, 2);
    float m  = fmaxf(v0, fmaxf(v1, v2));
    float e0 = ex2f((v0 - m) * LOG2E);
    float e1 = ex2f((v1 - m) * LOG2E);
    float e2 = ex2f((v2 - m) * LOG2E);
    float inv = rcpf(e0 + e1 + e2);
    if (lane == 0) {
        out[b * 3 + 0] = e0 * inv;
        out[b * 3 + 1] = e1 * inv;
        out[b * 3 + 2] = e2 * inv;
    }
}

extern "C" void kernel_launch(void* const* d_in, const int* in_sizes, int n_in,
                              void* d_out, int out_size) {
    (void)in_sizes; (void)n_in; (void)out_size;
    const float* x    = (const float*)d_in[0];
    const float* Wih1 = (const float*)d_in[1];
    const float* Whh1 = (const float*)d_in[2];
    const float* bih1 = (const float*)d_in[3];
    const float* bhh1 = (const float*)d_in[4];
    const float* Wih2 = (const float*)d_in[5];
    const float* Whh2 = (const float*)d_in[6];
    const float* bih2 = (const float*)d_in[7];
    const float* bhh2 = (const float*)d_in[8];
    const float* Wd1  = (const float*)d_in[9];
    const float* bd1  = (const float*)d_in[10];
    const float* Wd2  = (const float*)d_in[11];
    const float* bd2  = (const float*)d_in[12];
    const float* Wd3  = (const float*)d_in[13];
    const float* bd3  = (const float*)d_in[14];
    float* out = (float*)d_out;

    lstm_bf16_kernel<<<1024, 128>>>(x, Wih1, Whh1, bih1, bhh1,
                                    Wih2, Whh2, bih2, bhh2,
                                    Wd1, bd1, Wd2, bd2, Wd3, bd3, out);
}